// round 5
// baseline (speedup 1.0000x reference)
#include <cuda_runtime.h>
#include <cstdint>

// NCCLayer: argmax_d of normalized cross-correlation.
// input_compressed: [1, K=16, N=131072] fp32  (2,097,152 elems)
// cmat:             [K=16, D=1024]      fp32  (16,384 elems)
// out:              [N] FLOAT32 = argmax index over D (first occurrence on ties)
//
// R4 post-mortem: four kernels, four rel_err == EXACTLY 1.0. Root cause:
// output buffer is float32; integer bit patterns 0..1023 are denormals ~= 0,
// so the checker saw all-zeros => rel_err == 1.0 exactly. Fix: write
// (float)index. Indices <= 1023 are exact in fp32.
//
// Compute: scalar fp32 FFMA, fma-pipe bound (~2.1G FMAs => ~125-145us pred).

#define KK    16
#define DD    1024
#define DTILE 512
#define NTOT  131072
#define TPB   256

__global__ __launch_bounds__(TPB) void ncc_argmax_kernel(
    const float* __restrict__ x,
    const float* __restrict__ cmat,
    float* __restrict__ out)
{
    __shared__ float bs[KK][DTILE];   // 32 KB static shared

    const int tid = threadIdx.x;
    const int n   = blockIdx.x * TPB + tid;

    // ---- Normalize this thread's input column over K (registers) ----
    float a[KK];
    float s = 0.f;
    #pragma unroll
    for (int k = 0; k < KK; ++k) { a[k] = x[k * NTOT + n]; s += a[k]; }
    const float mu = s * (1.0f / KK);
    float ss = 0.f;
    #pragma unroll
    for (int k = 0; k < KK; ++k) { a[k] -= mu; ss += a[k] * a[k]; }
    const float inv = 1.0f / (sqrtf(ss) + 1e-10f);
    #pragma unroll
    for (int k = 0; k < KK; ++k) a[k] *= inv;

    float best  = -3.0e38f;
    int   besti = 0;

    #pragma unroll
    for (int t = 0; t < DD / DTILE; ++t) {
        if (t > 0) __syncthreads();   // previous tile fully consumed

        // ---- Normalize this tile's cmat columns into shared ----
        #pragma unroll
        for (int j = 0; j < DTILE / TPB; ++j) {
            const int dl = tid + j * TPB;       // local column
            const int d  = t * DTILE + dl;      // global column
            float v[KK];
            float s2 = 0.f;
            #pragma unroll
            for (int k = 0; k < KK; ++k) { v[k] = cmat[k * DD + d]; s2 += v[k]; }
            const float mu2 = s2 * (1.0f / KK);
            float ss2 = 0.f;
            #pragma unroll
            for (int k = 0; k < KK; ++k) { v[k] -= mu2; ss2 += v[k] * v[k]; }
            const float inv2 = 1.0f / (sqrtf(ss2) + 1e-10f);
            #pragma unroll
            for (int k = 0; k < KK; ++k) bs[k][dl] = v[k] * inv2;
        }
        __syncthreads();

        // ---- Sweep tile: 4 columns at a time, scalar FFMA, running argmax ----
        #pragma unroll 2
        for (int d = 0; d < DTILE; d += 4) {
            float acc0 = 0.f, acc1 = 0.f, acc2 = 0.f, acc3 = 0.f;
            #pragma unroll
            for (int k = 0; k < KK; ++k) {
                // uniform address across warp -> LDS.128 broadcast, conflict-free
                const float4 bb = *(const float4*)(&bs[k][d]);
                acc0 = fmaf(a[k], bb.x, acc0);
                acc1 = fmaf(a[k], bb.y, acc1);
                acc2 = fmaf(a[k], bb.z, acc2);
                acc3 = fmaf(a[k], bb.w, acc3);
            }
            const int dg = t * DTILE + d;
            // strict '>' ascending scan == jnp.argmax first-occurrence semantics
            if (acc0 > best) { best = acc0; besti = dg;     }
            if (acc1 > best) { best = acc1; besti = dg + 1; }
            if (acc2 > best) { best = acc2; besti = dg + 2; }
            if (acc3 > best) { best = acc3; besti = dg + 3; }
        }
    }

    out[n] = (float)besti;   // FLOAT output: index value as fp32 (exact <= 2^24)
}

extern "C" void kernel_launch(void* const* d_in, const int* in_sizes, int n_in,
                              void* d_out, int out_size)
{
    // Select inputs by element count — immune to metadata ordering.
    const float* x;
    const float* cmat;
    if (in_sizes[0] >= in_sizes[1]) {
        x    = (const float*)d_in[0];
        cmat = (const float*)d_in[1];
    } else {
        x    = (const float*)d_in[1];
        cmat = (const float*)d_in[0];
    }
    float* out = (float*)d_out;

    ncc_argmax_kernel<<<NTOT / TPB, TPB>>>(x, cmat, out);
}

// round 6
// speedup vs baseline: 1.5236x; 1.5236x over previous
#include <cuda_runtime.h>
#include <cstdint>

// NCCLayer: argmax_d of normalized cross-correlation. out[n] = (float)argmax.
// R5 passed (160us, scalar). R6: (1) 2 n-columns per thread to halve LDS
// pressure (L1 pipe was 72% = binding), (2) packed fma.rn.f32x2 across
// d-pairs to halve fma-pipe ops (R1/R2 "fma2 broken" was a misdiagnosis of
// the output-dtype bug). Same k-ascending fp32 accumulation order => bitwise
// identical dots => rel_err stays exactly 0.

#define KK    16
#define DD    1024
#define DTILE 512
#define NTOT  131072
#define TPB   128
#define NPT   2   // n-columns per thread

__device__ __forceinline__ uint64_t pack2(float x, float y) {
    uint64_t r;
    asm("mov.b64 %0, {%1, %2};" : "=l"(r) : "f"(x), "f"(y));
    return r;
}
__device__ __forceinline__ void unpack2(uint64_t v, float& x, float& y) {
    asm("mov.b64 {%0, %1}, %2;" : "=f"(x), "=f"(y) : "l"(v));
}
__device__ __forceinline__ uint64_t fma2(uint64_t a, uint64_t b, uint64_t c) {
    uint64_t d;
    asm("fma.rn.f32x2 %0, %1, %2, %3;" : "=l"(d) : "l"(a), "l"(b), "l"(c));
    return d;
}

__global__ __launch_bounds__(TPB) void ncc_argmax_kernel(
    const float* __restrict__ x,
    const float* __restrict__ cmat,
    float* __restrict__ out)
{
    __shared__ float bs[KK][DTILE];   // 32 KB static shared

    const int tid = threadIdx.x;
    const int n0  = blockIdx.x * (TPB * NPT) + tid;   // and n0 + TPB

    // ---- Normalize both input columns over K; keep packed {a,a} copies ----
    uint64_t ap[NPT][KK];
    #pragma unroll
    for (int p = 0; p < NPT; ++p) {
        const int n = n0 + p * TPB;
        float a[KK];
        float s = 0.f;
        #pragma unroll
        for (int k = 0; k < KK; ++k) { a[k] = x[k * NTOT + n]; s += a[k]; }
        const float mu = s * (1.0f / KK);
        float ss = 0.f;
        #pragma unroll
        for (int k = 0; k < KK; ++k) { a[k] -= mu; ss += a[k] * a[k]; }
        const float inv = 1.0f / (sqrtf(ss) + 1e-10f);
        #pragma unroll
        for (int k = 0; k < KK; ++k) {
            const float av = a[k] * inv;
            ap[p][k] = pack2(av, av);
        }
    }

    float best[NPT]  = { -3.0e38f, -3.0e38f };
    int   besti[NPT] = { 0, 0 };

    #pragma unroll
    for (int t = 0; t < DD / DTILE; ++t) {
        if (t > 0) __syncthreads();   // previous tile fully consumed

        // ---- Normalize this tile's cmat columns into shared ----
        #pragma unroll
        for (int j = 0; j < DTILE / TPB; ++j) {
            const int dl = tid + j * TPB;       // local column
            const int d  = t * DTILE + dl;      // global column
            float v[KK];
            float s2 = 0.f;
            #pragma unroll
            for (int k = 0; k < KK; ++k) { v[k] = cmat[k * DD + d]; s2 += v[k]; }
            const float mu2 = s2 * (1.0f / KK);
            float ss2 = 0.f;
            #pragma unroll
            for (int k = 0; k < KK; ++k) { v[k] -= mu2; ss2 += v[k] * v[k]; }
            const float inv2 = 1.0f / (sqrtf(ss2) + 1e-10f);
            #pragma unroll
            for (int k = 0; k < KK; ++k) bs[k][dl] = v[k] * inv2;
        }
        __syncthreads();

        // ---- Sweep tile: 4 d-columns x 2 n-columns, packed f32x2 FMA ----
        #pragma unroll 2
        for (int d = 0; d < DTILE; d += 4) {
            uint64_t acc00 = 0ull, acc01 = 0ull;   // n0: d[0:2), d[2:4)
            uint64_t acc10 = 0ull, acc11 = 0ull;   // n1
            #pragma unroll
            for (int k = 0; k < KK; ++k) {
                // uniform address across warp -> LDS.128 broadcast
                const ulonglong2 bb = *(const ulonglong2*)(&bs[k][d]);
                acc00 = fma2(ap[0][k], bb.x, acc00);
                acc01 = fma2(ap[0][k], bb.y, acc01);
                acc10 = fma2(ap[1][k], bb.x, acc10);
                acc11 = fma2(ap[1][k], bb.y, acc11);
            }
            const int dg = t * DTILE + d;
            float v0, v1, v2, v3;
            unpack2(acc00, v0, v1);
            unpack2(acc01, v2, v3);
            if (v0 > best[0]) { best[0] = v0; besti[0] = dg;     }
            if (v1 > best[0]) { best[0] = v1; besti[0] = dg + 1; }
            if (v2 > best[0]) { best[0] = v2; besti[0] = dg + 2; }
            if (v3 > best[0]) { best[0] = v3; besti[0] = dg + 3; }
            unpack2(acc10, v0, v1);
            unpack2(acc11, v2, v3);
            if (v0 > best[1]) { best[1] = v0; besti[1] = dg;     }
            if (v1 > best[1]) { best[1] = v1; besti[1] = dg + 1; }
            if (v2 > best[1]) { best[1] = v2; besti[1] = dg + 2; }
            if (v3 > best[1]) { best[1] = v3; besti[1] = dg + 3; }
        }
    }

    #pragma unroll
    for (int p = 0; p < NPT; ++p)
        out[n0 + p * TPB] = (float)besti[p];
}

extern "C" void kernel_launch(void* const* d_in, const int* in_sizes, int n_in,
                              void* d_out, int out_size)
{
    // Select inputs by element count — immune to metadata ordering.
    const float* x;
    const float* cmat;
    if (in_sizes[0] >= in_sizes[1]) {
        x    = (const float*)d_in[0];
        cmat = (const float*)d_in[1];
    } else {
        x    = (const float*)d_in[1];
        cmat = (const float*)d_in[0];
    }
    float* out = (float*)d_out;

    ncc_argmax_kernel<<<NTOT / (TPB * NPT), TPB>>>(x, cmat, out);
}

// round 7
// speedup vs baseline: 1.7640x; 1.1578x over previous
#include <cuda_runtime.h>
#include <cstdint>

// NCCLayer argmax. R7: split D into 4 block-splits (4x warps: 3.46 -> ~5+/SMSP,
// issue was 56%), FMNMX tournament argmax (kills FSETP-13cyc serial chain),
// tiny combine kernel. Per-d dot math bit-identical to R6 (rel_err must stay 0).

#define KK     16
#define DD     1024
#define NSPLIT 4
#define DSPL   (DD / NSPLIT)        // 256 d-bins per split
#define NTOT   131072
#define TPB    128
#define NPT    2
#define NBLK   (NTOT / (TPB * NPT)) // 512 n-blocks

__device__ float2 g_part[NSPLIT * NTOT];  // (val, idx) partials, 4 MB static

__device__ __forceinline__ uint64_t pack2(float x, float y) {
    uint64_t r;
    asm("mov.b64 %0, {%1, %2};" : "=l"(r) : "f"(x), "f"(y));
    return r;
}
__device__ __forceinline__ void unpack2(uint64_t v, float& x, float& y) {
    asm("mov.b64 {%0, %1}, %2;" : "=f"(x), "=f"(y) : "l"(v));
}
__device__ __forceinline__ uint64_t fma2(uint64_t a, uint64_t b, uint64_t c) {
    uint64_t d;
    asm("fma.rn.f32x2 %0, %1, %2, %3;" : "=l"(d) : "l"(a), "l"(b), "l"(c));
    return d;
}

__global__ __launch_bounds__(TPB) void ncc_partial_kernel(
    const float* __restrict__ x,
    const float* __restrict__ cmat)
{
    __shared__ float bs[KK][DSPL];    // 16 KB static shared

    const int tid = threadIdx.x;
    const int n0  = blockIdx.x * (TPB * NPT) + tid;   // and n0 + TPB
    const int spl = blockIdx.y;
    const int d0  = spl * DSPL;

    // ---- Normalize this split's cmat columns into shared (2 cols/thread) ----
    #pragma unroll
    for (int j = 0; j < DSPL / TPB; ++j) {
        const int dl = tid + j * TPB;
        const int d  = d0 + dl;
        float v[KK];
        float s2 = 0.f;
        #pragma unroll
        for (int k = 0; k < KK; ++k) { v[k] = cmat[k * DD + d]; s2 += v[k]; }
        const float mu2 = s2 * (1.0f / KK);
        float ss2 = 0.f;
        #pragma unroll
        for (int k = 0; k < KK; ++k) { v[k] -= mu2; ss2 += v[k] * v[k]; }
        const float inv2 = 1.0f / (sqrtf(ss2) + 1e-10f);
        #pragma unroll
        for (int k = 0; k < KK; ++k) bs[k][dl] = v[k] * inv2;
    }

    // ---- Normalize this thread's two input columns; packed {a,a} copies ----
    uint64_t ap[NPT][KK];
    #pragma unroll
    for (int p = 0; p < NPT; ++p) {
        const int n = n0 + p * TPB;
        float a[KK];
        float s = 0.f;
        #pragma unroll
        for (int k = 0; k < KK; ++k) { a[k] = x[k * NTOT + n]; s += a[k]; }
        const float mu = s * (1.0f / KK);
        float ss = 0.f;
        #pragma unroll
        for (int k = 0; k < KK; ++k) { a[k] -= mu; ss += a[k] * a[k]; }
        const float inv = 1.0f / (sqrtf(ss) + 1e-10f);
        #pragma unroll
        for (int k = 0; k < KK; ++k) {
            const float av = a[k] * inv;
            ap[p][k] = pack2(av, av);
        }
    }
    __syncthreads();

    float best[NPT]  = { -3.0e38f, -3.0e38f };
    int   besti[NPT] = { 0, 0 };

    // ---- Sweep split: 4 d-columns x 2 n-columns, packed f32x2 FMA ----
    #pragma unroll 2
    for (int d = 0; d < DSPL; d += 4) {
        uint64_t acc00 = 0ull, acc01 = 0ull;   // n0: d[0:2), d[2:4)
        uint64_t acc10 = 0ull, acc11 = 0ull;   // n1
        #pragma unroll
        for (int k = 0; k < KK; ++k) {
            // uniform address across warp -> LDS.128 broadcast
            const ulonglong2 bb = *(const ulonglong2*)(&bs[k][d]);
            acc00 = fma2(ap[0][k], bb.x, acc00);
            acc01 = fma2(ap[0][k], bb.y, acc01);
            acc10 = fma2(ap[1][k], bb.x, acc10);
            acc11 = fma2(ap[1][k], bb.y, acc11);
        }
        const int dg = d0 + d;

        // Tournament argmax: FMNMX tree (exact, lat 4) + first-occurrence index.
        {
            float v0, v1, v2, v3;
            unpack2(acc00, v0, v1);
            unpack2(acc01, v2, v3);
            const float m01 = fmaxf(v0, v1), m23 = fmaxf(v2, v3);
            const float m   = fmaxf(m01, m23);
            const int j = (v0 == m) ? 0 : (v1 == m) ? 1 : (v2 == m) ? 2 : 3;
            const bool gt = m > best[0];
            besti[0] = gt ? (dg + j) : besti[0];
            best[0]  = fmaxf(best[0], m);
        }
        {
            float v0, v1, v2, v3;
            unpack2(acc10, v0, v1);
            unpack2(acc11, v2, v3);
            const float m01 = fmaxf(v0, v1), m23 = fmaxf(v2, v3);
            const float m   = fmaxf(m01, m23);
            const int j = (v0 == m) ? 0 : (v1 == m) ? 1 : (v2 == m) ? 2 : 3;
            const bool gt = m > best[1];
            besti[1] = gt ? (dg + j) : besti[1];
            best[1]  = fmaxf(best[1], m);
        }
    }

    #pragma unroll
    for (int p = 0; p < NPT; ++p)
        g_part[spl * NTOT + n0 + p * TPB] = make_float2(best[p], (float)besti[p]);
}

__global__ __launch_bounds__(256) void ncc_combine_kernel(float* __restrict__ out)
{
    const int n = blockIdx.x * 256 + threadIdx.x;
    float2 b = g_part[n];                       // split 0
    #pragma unroll
    for (int s = 1; s < NSPLIT; ++s) {
        const float2 c = g_part[s * NTOT + n];
        // strict '>' ascending split order == global first-occurrence
        if (c.x > b.x) b = c;
    }
    out[n] = b.y;
}

extern "C" void kernel_launch(void* const* d_in, const int* in_sizes, int n_in,
                              void* d_out, int out_size)
{
    // Select inputs by element count — immune to metadata ordering.
    const float* x;
    const float* cmat;
    if (in_sizes[0] >= in_sizes[1]) {
        x    = (const float*)d_in[0];
        cmat = (const float*)d_in[1];
    } else {
        x    = (const float*)d_in[1];
        cmat = (const float*)d_in[0];
    }
    float* out = (float*)d_out;

    dim3 grid(NBLK, NSPLIT);
    ncc_partial_kernel<<<grid, TPB>>>(x, cmat);
    ncc_combine_kernel<<<NTOT / 256, 256>>>(out);
}